// round 12
// baseline (speedup 1.0000x reference)
#include <cuda_runtime.h>
#include <cuda_fp16.h>
#include <cstdint>

#define NUM_CODES 100000
#define DIM 64
#define NVISITS 65536
#define LCODES 48

// fp16 pre-scaled tangent table. Row = 64 halfs = 128 B = one L2 line.
// ~12.8 MB, L2-resident.
__device__ __align__(16) __half2 g_tang[(size_t)NUM_CODES * (DIM / 2)];

// ---------------------------------------------------------------------------
// Pass 1: tang[c] = (atanh(min(||emb_c||,1-1e-7)) / max(||emb_c||,1e-15)) * emb_c
// One warp per row; lane owns 2 dims. Butterfly norm reduce, Taylor atanh(x)/x
// in the small-norm regime (data: ||x|| ~ 0.008).
// ---------------------------------------------------------------------------
__global__ void __launch_bounds__(256) build_tangents(const float* __restrict__ emb) {
    int warp = (blockIdx.x * blockDim.x + threadIdx.x) >> 5;
    int lane = threadIdx.x & 31;
    if (warp >= NUM_CODES) return;

    const float2 v = reinterpret_cast<const float2*>(emb + (size_t)warp * DIM)[lane];
    float ss = v.x * v.x + v.y * v.y;
    #pragma unroll
    for (int o = 16; o; o >>= 1)
        ss += __shfl_xor_sync(0xffffffffu, ss, o);

    float s;
    if (ss < 0.09f) {
        // atanh(x)/x = 1 + y/3 + y^2/5 + y^3/7 + y^4/9, y = x^2 = ss.
        s = 1.0f + ss * (0.33333334f + ss * (0.2f + ss * (0.14285715f + ss * 0.11111111f)));
    } else {
        float n = fmaxf(sqrtf(ss), 1e-15f);
        float a = fminf(n, 1.0f - 1e-7f);
        s = atanhf(a) / n;
    }

    g_tang[(size_t)warp * (DIM / 2) + lane] =
        __float22half2_rn(make_float2(s * v.x, s * v.y));
}

// half2 add on raw u32 payloads (HADD2).
__device__ __forceinline__ uint32_t hadd2u(uint32_t a, uint32_t b) {
    uint32_t r;
    asm("add.rn.f16x2 %0, %1, %2;" : "=r"(r) : "r"(a), "r"(b));
    return r;
}

// Convert one half2 to f32x2 and add into a packed f32x2 accumulator.
__device__ __forceinline__ void hacc2(uint32_t h2, unsigned long long& acc) {
    asm("{\n\t"
        ".reg .f16 l, h;\n\t"
        ".reg .f32 fl, fh;\n\t"
        ".reg .b64 fv;\n\t"
        "mov.b32 {l, h}, %1;\n\t"
        "cvt.f32.f16 fl, l;\n\t"
        "cvt.f32.f16 fh, h;\n\t"
        "mov.b64 fv, {fl, fh};\n\t"
        "add.rn.f32x2 %0, %0, fv;\n\t"
        "}" : "+l"(acc) : "r"(h2));
}

// Predicated 16B gather: returns zeros when pred is false, no memory traffic.
__device__ __forceinline__ uint4 gather_pred(bool pred, const char* p) {
    uint4 r = make_uint4(0u, 0u, 0u, 0u);
    if (pred) r = *reinterpret_cast<const uint4*>(p);
    return r;
}

// ---------------------------------------------------------------------------
// Pass 2: out[visit] = mean over valid codes of tang[code].
// QUARTER-WARP PER VISIT; predicated gathers (A/B-proven vs zero-row clamp).
// Supergroup of 8 codes processed as TWO WAVES of 4 gathers: wave 1 folds to
// four half2 partials before wave 2 loads, capping live registers at
// 4 x uint4 + 4 words. This fits __launch_bounds__(256,6) (~42 regs), lifting
// occupancy ~65% -> ~78% to hide the ~250cyc L2 gather latency. The 8-wide
// fp16 tree still pays only 6 fp16->fp32 conversions per component stream.
// ---------------------------------------------------------------------------
__global__ void __launch_bounds__(256, 6) visit_mean(const int* __restrict__ ids,
                                                     float* __restrict__ out) {
    int warp  = (blockIdx.x * blockDim.x + threadIdx.x) >> 5;
    int lane  = threadIdx.x & 31;
    const int quarter = lane >> 3;
    const int ql      = lane & 7;          // 16B chunk within row: dims [8ql, 8ql+8)

    const int visit = warp * 4 + quarter;  // grid sized so this never overflows

    // 48 ids of this quarter's visit: 12 broadcast uint4 loads.
    const uint4* __restrict__ vid4 =
        reinterpret_cast<const uint4*>(ids + (size_t)visit * LCODES);

    const char* __restrict__ base = reinterpret_cast<const char*>(g_tang) + ql * 16;

    unsigned long long acc[4] = {0ull, 0ull, 0ull, 0ull};
    int cnt = 0;

    #pragma unroll
    for (int gg = 0; gg < 6; gg++) {       // 6 supergroups of 8 codes
        const uint4 idv0 = __ldg(vid4 + 2 * gg);
        const uint4 idv1 = __ldg(vid4 + 2 * gg + 1);

        const int i0 = (int)idv0.x, i1 = (int)idv0.y, i2 = (int)idv0.z, i3 = (int)idv0.w;
        const int i4 = (int)idv1.x, i5 = (int)idv1.y, i6 = (int)idv1.z, i7 = (int)idv1.w;
        cnt += (i0 >= 0) + (i1 >= 0) + (i2 >= 0) + (i3 >= 0)
             + (i4 >= 0) + (i5 >= 0) + (i6 >= 0) + (i7 >= 0);

        // Wave 1: 4 gathers, fold to 4 half2 partials.
        uint4 a = gather_pred(i0 >= 0, base + (size_t)(unsigned)i0 * 128u);
        uint4 b = gather_pred(i1 >= 0, base + (size_t)(unsigned)i1 * 128u);
        uint4 c = gather_pred(i2 >= 0, base + (size_t)(unsigned)i2 * 128u);
        uint4 d = gather_pred(i3 >= 0, base + (size_t)(unsigned)i3 * 128u);
        const uint32_t t0 = hadd2u(hadd2u(a.x, b.x), hadd2u(c.x, d.x));
        const uint32_t t1 = hadd2u(hadd2u(a.y, b.y), hadd2u(c.y, d.y));
        const uint32_t t2 = hadd2u(hadd2u(a.z, b.z), hadd2u(c.z, d.z));
        const uint32_t t3 = hadd2u(hadd2u(a.w, b.w), hadd2u(c.w, d.w));

        // Wave 2: 4 gathers, complete the 8-wide tree, one fp32 accumulate.
        a = gather_pred(i4 >= 0, base + (size_t)(unsigned)i4 * 128u);
        b = gather_pred(i5 >= 0, base + (size_t)(unsigned)i5 * 128u);
        c = gather_pred(i6 >= 0, base + (size_t)(unsigned)i6 * 128u);
        d = gather_pred(i7 >= 0, base + (size_t)(unsigned)i7 * 128u);
        hacc2(hadd2u(t0, hadd2u(hadd2u(a.x, b.x), hadd2u(c.x, d.x))), acc[0]);
        hacc2(hadd2u(t1, hadd2u(hadd2u(a.y, b.y), hadd2u(c.y, d.y))), acc[1]);
        hacc2(hadd2u(t2, hadd2u(hadd2u(a.z, b.z), hadd2u(c.z, d.z))), acc[2]);
        hacc2(hadd2u(t3, hadd2u(hadd2u(a.w, b.w), hadd2u(c.w, d.w))), acc[3]);
    }

    float f[8];
    #pragma unroll
    for (int j = 0; j < 4; j++) {
        f[2 * j]     = __uint_as_float((unsigned)(acc[j] & 0xffffffffull));
        f[2 * j + 1] = __uint_as_float((unsigned)(acc[j] >> 32));
    }

    const float inv = __fdividef(1.0f, fmaxf((float)cnt, 1.0f));
    float4 o0 = make_float4(f[0] * inv, f[1] * inv, f[2] * inv, f[3] * inv);
    float4 o1 = make_float4(f[4] * inv, f[5] * inv, f[6] * inv, f[7] * inv);
    float4* op = reinterpret_cast<float4*>(out + (size_t)visit * DIM + ql * 8);
    op[0] = o0;
    op[1] = o1;
}

extern "C" void kernel_launch(void* const* d_in, const int* in_sizes, int n_in,
                              void* d_out, int out_size) {
    const int*   code_ids = (const int*)d_in[0];   // [N, L] int32, -1 = pad
    const float* emb      = (const float*)d_in[1]; // [NUM_CODES, DIM] fp32
    float*       out      = (float*)d_out;         // [N, DIM] fp32

    (void)in_sizes; (void)n_in; (void)out_size;

    build_tangents<<<(NUM_CODES + 7) / 8, 256>>>(emb);
    // 32 visits per 256-thread block: 65536 / 32 = 2048 blocks.
    visit_mean<<<NVISITS / 32, 256>>>(code_ids, out);
}

// round 13
// speedup vs baseline: 1.0559x; 1.0559x over previous
#include <cuda_runtime.h>
#include <cuda_fp16.h>
#include <cstdint>

#define NUM_CODES 100000
#define DIM 64
#define NVISITS 65536
#define LCODES 48

// fp16 pre-scaled tangent table. Row = 64 halfs = 128 B = one L2 line.
// ~12.8 MB, L2-resident.
__device__ __align__(16) __half2 g_tang[(size_t)NUM_CODES * (DIM / 2)];

// ---------------------------------------------------------------------------
// Pass 1: tang[c] = (atanh(min(||emb_c||,1-1e-7)) / max(||emb_c||,1e-15)) * emb_c
// One warp per row; lane owns 2 dims. Butterfly norm reduce, Taylor atanh(x)/x
// in the small-norm regime (data: ||x|| ~ 0.008).
// ---------------------------------------------------------------------------
__global__ void __launch_bounds__(256) build_tangents(const float* __restrict__ emb) {
    int warp = (blockIdx.x * blockDim.x + threadIdx.x) >> 5;
    int lane = threadIdx.x & 31;
    if (warp >= NUM_CODES) return;

    const float2 v = reinterpret_cast<const float2*>(emb + (size_t)warp * DIM)[lane];
    float ss = v.x * v.x + v.y * v.y;
    #pragma unroll
    for (int o = 16; o; o >>= 1)
        ss += __shfl_xor_sync(0xffffffffu, ss, o);

    float s;
    if (ss < 0.09f) {
        // atanh(x)/x = 1 + y/3 + y^2/5 + y^3/7 + y^4/9, y = x^2 = ss.
        s = 1.0f + ss * (0.33333334f + ss * (0.2f + ss * (0.14285715f + ss * 0.11111111f)));
    } else {
        float n = fmaxf(sqrtf(ss), 1e-15f);
        float a = fminf(n, 1.0f - 1e-7f);
        s = atanhf(a) / n;
    }

    g_tang[(size_t)warp * (DIM / 2) + lane] =
        __float22half2_rn(make_float2(s * v.x, s * v.y));
}

// half2 add on raw u32 payloads (HADD2).
__device__ __forceinline__ uint32_t hadd2u(uint32_t a, uint32_t b) {
    uint32_t r;
    asm("add.rn.f16x2 %0, %1, %2;" : "=r"(r) : "r"(a), "r"(b));
    return r;
}

// Convert one half2 to f32x2 and add into a packed f32x2 accumulator.
__device__ __forceinline__ void hacc2(uint32_t h2, unsigned long long& acc) {
    asm("{\n\t"
        ".reg .f16 l, h;\n\t"
        ".reg .f32 fl, fh;\n\t"
        ".reg .b64 fv;\n\t"
        "mov.b32 {l, h}, %1;\n\t"
        "cvt.f32.f16 fl, l;\n\t"
        "cvt.f32.f16 fh, h;\n\t"
        "mov.b64 fv, {fl, fh};\n\t"
        "add.rn.f32x2 %0, %0, fv;\n\t"
        "}" : "+l"(acc) : "r"(h2));
}

// Predicated 16B gather: returns zeros when pred is false, no memory traffic.
__device__ __forceinline__ uint4 gather_pred(bool pred, const char* p) {
    uint4 r = make_uint4(0u, 0u, 0u, 0u);
    if (pred) r = *reinterpret_cast<const uint4*>(p);
    return r;
}

// ---------------------------------------------------------------------------
// Pass 2: out[visit] = mean over valid codes of tang[code].
// QUARTER-WARP PER VISIT; predicated gathers; 8-wide fp16 tree (R11 base,
// best measured). NEW: the id pair for supergroup g+1 is prefetched right
// after supergroup g's gathers are issued, so the ~234cyc id-load latency
// overlaps the gather wait + arithmetic instead of heading every chain.
// ---------------------------------------------------------------------------
__global__ void __launch_bounds__(256, 5) visit_mean(const int* __restrict__ ids,
                                                     float* __restrict__ out) {
    int warp  = (blockIdx.x * blockDim.x + threadIdx.x) >> 5;
    int lane  = threadIdx.x & 31;
    const int quarter = lane >> 3;
    const int ql      = lane & 7;          // 16B chunk within row: dims [8ql, 8ql+8)

    const int visit = warp * 4 + quarter;  // grid sized so this never overflows

    // 48 ids of this quarter's visit: 12 broadcast uint4 loads (2 per group).
    const uint4* __restrict__ vid4 =
        reinterpret_cast<const uint4*>(ids + (size_t)visit * LCODES);

    const char* __restrict__ base = reinterpret_cast<const char*>(g_tang) + ql * 16;

    unsigned long long acc[4] = {0ull, 0ull, 0ull, 0ull};
    int cnt = 0;

    // Prime the id pipeline with supergroup 0's ids.
    uint4 idv0 = __ldg(vid4 + 0);
    uint4 idv1 = __ldg(vid4 + 1);

    #pragma unroll
    for (int gg = 0; gg < 6; gg++) {       // 6 supergroups of 8 codes
        const int i0 = (int)idv0.x, i1 = (int)idv0.y, i2 = (int)idv0.z, i3 = (int)idv0.w;
        const int i4 = (int)idv1.x, i5 = (int)idv1.y, i6 = (int)idv1.z, i7 = (int)idv1.w;
        cnt += (i0 >= 0) + (i1 >= 0) + (i2 >= 0) + (i3 >= 0)
             + (i4 >= 0) + (i5 >= 0) + (i6 >= 0) + (i7 >= 0);

        // Issue all 8 gathers of this supergroup.
        const uint4 a = gather_pred(i0 >= 0, base + (size_t)(unsigned)i0 * 128u);
        const uint4 b = gather_pred(i1 >= 0, base + (size_t)(unsigned)i1 * 128u);
        const uint4 c = gather_pred(i2 >= 0, base + (size_t)(unsigned)i2 * 128u);
        const uint4 d = gather_pred(i3 >= 0, base + (size_t)(unsigned)i3 * 128u);
        const uint4 e = gather_pred(i4 >= 0, base + (size_t)(unsigned)i4 * 128u);
        const uint4 h = gather_pred(i5 >= 0, base + (size_t)(unsigned)i5 * 128u);
        const uint4 p = gather_pred(i6 >= 0, base + (size_t)(unsigned)i6 * 128u);
        const uint4 q = gather_pred(i7 >= 0, base + (size_t)(unsigned)i7 * 128u);

        // Prefetch next supergroup's ids while the gathers are in flight.
        if (gg < 5) {
            idv0 = __ldg(vid4 + 2 * gg + 2);
            idv1 = __ldg(vid4 + 2 * gg + 3);
        }

        // 8-wide balanced fp16 tree per component, single fp32 accumulate.
        hacc2(hadd2u(hadd2u(hadd2u(a.x, b.x), hadd2u(c.x, d.x)),
                     hadd2u(hadd2u(e.x, h.x), hadd2u(p.x, q.x))), acc[0]);
        hacc2(hadd2u(hadd2u(hadd2u(a.y, b.y), hadd2u(c.y, d.y)),
                     hadd2u(hadd2u(e.y, h.y), hadd2u(p.y, q.y))), acc[1]);
        hacc2(hadd2u(hadd2u(hadd2u(a.z, b.z), hadd2u(c.z, d.z)),
                     hadd2u(hadd2u(e.z, h.z), hadd2u(p.z, q.z))), acc[2]);
        hacc2(hadd2u(hadd2u(hadd2u(a.w, b.w), hadd2u(c.w, d.w)),
                     hadd2u(hadd2u(e.w, h.w), hadd2u(p.w, q.w))), acc[3]);
    }

    float f[8];
    #pragma unroll
    for (int j = 0; j < 4; j++) {
        f[2 * j]     = __uint_as_float((unsigned)(acc[j] & 0xffffffffull));
        f[2 * j + 1] = __uint_as_float((unsigned)(acc[j] >> 32));
    }

    const float inv = __fdividef(1.0f, fmaxf((float)cnt, 1.0f));
    float4 o0 = make_float4(f[0] * inv, f[1] * inv, f[2] * inv, f[3] * inv);
    float4 o1 = make_float4(f[4] * inv, f[5] * inv, f[6] * inv, f[7] * inv);
    float4* op = reinterpret_cast<float4*>(out + (size_t)visit * DIM + ql * 8);
    op[0] = o0;
    op[1] = o1;
}

extern "C" void kernel_launch(void* const* d_in, const int* in_sizes, int n_in,
                              void* d_out, int out_size) {
    const int*   code_ids = (const int*)d_in[0];   // [N, L] int32, -1 = pad
    const float* emb      = (const float*)d_in[1]; // [NUM_CODES, DIM] fp32
    float*       out      = (float*)d_out;         // [N, DIM] fp32

    (void)in_sizes; (void)n_in; (void)out_size;

    build_tangents<<<(NUM_CODES + 7) / 8, 256>>>(emb);
    // 32 visits per 256-thread block: 65536 / 32 = 2048 blocks.
    visit_mean<<<NVISITS / 32, 256>>>(code_ids, out);
}

// round 14
// speedup vs baseline: 1.0645x; 1.0082x over previous
#include <cuda_runtime.h>
#include <cuda_fp16.h>
#include <cstdint>

#define NUM_CODES 100000
#define DIM 64
#define NVISITS 65536
#define LCODES 48
#define VISITS_PER_BLOCK 32
#define IDV4_PER_VISIT 12                       // 48 ids = 12 uint4
#define IDV4_PER_BLOCK (VISITS_PER_BLOCK * IDV4_PER_VISIT)   // 384

// fp16 pre-scaled tangent table. Row = 64 halfs = 128 B = one L2 line.
// ~12.8 MB, L2-resident.
__device__ __align__(16) __half2 g_tang[(size_t)NUM_CODES * (DIM / 2)];

// ---------------------------------------------------------------------------
// Pass 1: tang[c] = (atanh(min(||emb_c||,1-1e-7)) / max(||emb_c||,1e-15)) * emb_c
// One warp per row; lane owns 2 dims. Butterfly norm reduce, Taylor atanh(x)/x
// in the small-norm regime (data: ||x|| ~ 0.008).
// ---------------------------------------------------------------------------
__global__ void __launch_bounds__(256) build_tangents(const float* __restrict__ emb) {
    int warp = (blockIdx.x * blockDim.x + threadIdx.x) >> 5;
    int lane = threadIdx.x & 31;
    if (warp >= NUM_CODES) return;

    const float2 v = reinterpret_cast<const float2*>(emb + (size_t)warp * DIM)[lane];
    float ss = v.x * v.x + v.y * v.y;
    #pragma unroll
    for (int o = 16; o; o >>= 1)
        ss += __shfl_xor_sync(0xffffffffu, ss, o);

    float s;
    if (ss < 0.09f) {
        // atanh(x)/x = 1 + y/3 + y^2/5 + y^3/7 + y^4/9, y = x^2 = ss.
        s = 1.0f + ss * (0.33333334f + ss * (0.2f + ss * (0.14285715f + ss * 0.11111111f)));
    } else {
        float n = fmaxf(sqrtf(ss), 1e-15f);
        float a = fminf(n, 1.0f - 1e-7f);
        s = atanhf(a) / n;
    }

    g_tang[(size_t)warp * (DIM / 2) + lane] =
        __float22half2_rn(make_float2(s * v.x, s * v.y));
}

// half2 add on raw u32 payloads (HADD2).
__device__ __forceinline__ uint32_t hadd2u(uint32_t a, uint32_t b) {
    uint32_t r;
    asm("add.rn.f16x2 %0, %1, %2;" : "=r"(r) : "r"(a), "r"(b));
    return r;
}

// Convert one half2 to f32x2 and add into a packed f32x2 accumulator.
__device__ __forceinline__ void hacc2(uint32_t h2, unsigned long long& acc) {
    asm("{\n\t"
        ".reg .f16 l, h;\n\t"
        ".reg .f32 fl, fh;\n\t"
        ".reg .b64 fv;\n\t"
        "mov.b32 {l, h}, %1;\n\t"
        "cvt.f32.f16 fl, l;\n\t"
        "cvt.f32.f16 fh, h;\n\t"
        "mov.b64 fv, {fl, fh};\n\t"
        "add.rn.f32x2 %0, %0, fv;\n\t"
        "}" : "+l"(acc) : "r"(h2));
}

// Predicated 16B gather: returns zeros when pred is false, no memory traffic.
__device__ __forceinline__ uint4 gather_pred(bool pred, const char* p) {
    uint4 r = make_uint4(0u, 0u, 0u, 0u);
    if (pred) r = *reinterpret_cast<const uint4*>(p);
    return r;
}

// ---------------------------------------------------------------------------
// Pass 2: out[visit] = mean over valid codes of tang[code].
// QUARTER-WARP PER VISIT; predicated gathers; 8-wide fp16 tree (R11 base).
// NEW: ids staged through SHARED MEMORY. The block's 32 visits own a
// contiguous 6KB id slab, loaded fully coalesced (48 L1tex wavefronts per
// block instead of 384 for per-quarter broadcast LDGs -- ids were ~25% of
// the kernel's global wavefront budget). Quarters then read id pairs via
// conflict-free broadcast LDS.128.
// ---------------------------------------------------------------------------
__global__ void __launch_bounds__(256, 5) visit_mean(const int* __restrict__ ids,
                                                     float* __restrict__ out) {
    __shared__ __align__(16) uint4 sids[IDV4_PER_BLOCK];   // 6 KB

    const int tid  = threadIdx.x;
    const int warp = tid >> 5;
    const int lane = tid & 31;
    const int quarter = lane >> 3;
    const int ql      = lane & 7;          // 16B chunk within row: dims [8ql, 8ql+8)

    // Stage the block's ids: 384 uint4, coalesced.
    {
        const uint4* __restrict__ gids = reinterpret_cast<const uint4*>(
            ids + (size_t)blockIdx.x * VISITS_PER_BLOCK * LCODES);
        sids[tid] = __ldg(gids + tid);                       // 0..255
        if (tid < IDV4_PER_BLOCK - 256)
            sids[256 + tid] = __ldg(gids + 256 + tid);       // 256..383
    }
    __syncthreads();

    const int lvisit = warp * 4 + quarter;                   // visit within block
    const int visit  = blockIdx.x * VISITS_PER_BLOCK + lvisit;
    const uint4* __restrict__ vid4 = sids + lvisit * IDV4_PER_VISIT;

    const char* __restrict__ base = reinterpret_cast<const char*>(g_tang) + ql * 16;

    unsigned long long acc[4] = {0ull, 0ull, 0ull, 0ull};
    int cnt = 0;

    #pragma unroll
    for (int gg = 0; gg < 6; gg++) {       // 6 supergroups of 8 codes
        const uint4 idv0 = vid4[2 * gg];
        const uint4 idv1 = vid4[2 * gg + 1];

        const int i0 = (int)idv0.x, i1 = (int)idv0.y, i2 = (int)idv0.z, i3 = (int)idv0.w;
        const int i4 = (int)idv1.x, i5 = (int)idv1.y, i6 = (int)idv1.z, i7 = (int)idv1.w;
        cnt += (i0 >= 0) + (i1 >= 0) + (i2 >= 0) + (i3 >= 0)
             + (i4 >= 0) + (i5 >= 0) + (i6 >= 0) + (i7 >= 0);

        const uint4 a = gather_pred(i0 >= 0, base + (size_t)(unsigned)i0 * 128u);
        const uint4 b = gather_pred(i1 >= 0, base + (size_t)(unsigned)i1 * 128u);
        const uint4 c = gather_pred(i2 >= 0, base + (size_t)(unsigned)i2 * 128u);
        const uint4 d = gather_pred(i3 >= 0, base + (size_t)(unsigned)i3 * 128u);
        const uint4 e = gather_pred(i4 >= 0, base + (size_t)(unsigned)i4 * 128u);
        const uint4 h = gather_pred(i5 >= 0, base + (size_t)(unsigned)i5 * 128u);
        const uint4 p = gather_pred(i6 >= 0, base + (size_t)(unsigned)i6 * 128u);
        const uint4 q = gather_pred(i7 >= 0, base + (size_t)(unsigned)i7 * 128u);

        // 8-wide balanced fp16 tree per component, single fp32 accumulate.
        hacc2(hadd2u(hadd2u(hadd2u(a.x, b.x), hadd2u(c.x, d.x)),
                     hadd2u(hadd2u(e.x, h.x), hadd2u(p.x, q.x))), acc[0]);
        hacc2(hadd2u(hadd2u(hadd2u(a.y, b.y), hadd2u(c.y, d.y)),
                     hadd2u(hadd2u(e.y, h.y), hadd2u(p.y, q.y))), acc[1]);
        hacc2(hadd2u(hadd2u(hadd2u(a.z, b.z), hadd2u(c.z, d.z)),
                     hadd2u(hadd2u(e.z, h.z), hadd2u(p.z, q.z))), acc[2]);
        hacc2(hadd2u(hadd2u(hadd2u(a.w, b.w), hadd2u(c.w, d.w)),
                     hadd2u(hadd2u(e.w, h.w), hadd2u(p.w, q.w))), acc[3]);
    }

    float f[8];
    #pragma unroll
    for (int j = 0; j < 4; j++) {
        f[2 * j]     = __uint_as_float((unsigned)(acc[j] & 0xffffffffull));
        f[2 * j + 1] = __uint_as_float((unsigned)(acc[j] >> 32));
    }

    const float inv = __fdividef(1.0f, fmaxf((float)cnt, 1.0f));
    float4 o0 = make_float4(f[0] * inv, f[1] * inv, f[2] * inv, f[3] * inv);
    float4 o1 = make_float4(f[4] * inv, f[5] * inv, f[6] * inv, f[7] * inv);
    float4* op = reinterpret_cast<float4*>(out + (size_t)visit * DIM + ql * 8);
    op[0] = o0;
    op[1] = o1;
}

extern "C" void kernel_launch(void* const* d_in, const int* in_sizes, int n_in,
                              void* d_out, int out_size) {
    const int*   code_ids = (const int*)d_in[0];   // [N, L] int32, -1 = pad
    const float* emb      = (const float*)d_in[1]; // [NUM_CODES, DIM] fp32
    float*       out      = (float*)d_out;         // [N, DIM] fp32

    (void)in_sizes; (void)n_in; (void)out_size;

    build_tangents<<<(NUM_CODES + 7) / 8, 256>>>(emb);
    // 32 visits per 256-thread block: 65536 / 32 = 2048 blocks.
    visit_mean<<<NVISITS / VISITS_PER_BLOCK, 256>>>(code_ids, out);
}

// round 15
// speedup vs baseline: 1.1318x; 1.0632x over previous
#include <cuda_runtime.h>
#include <cuda_fp16.h>
#include <cstdint>

#define NUM_CODES 100000
#define DIM 64
#define NVISITS 65536
#define LCODES 48
#define VISITS_PER_BLOCK 32
#define IDV4_PER_VISIT 12                       // 48 ids = 12 uint4
#define IDV4_PER_BLOCK (VISITS_PER_BLOCK * IDV4_PER_VISIT)   // 384

// fp16 pre-scaled tangent table. Row = 64 halfs = 128 B = one L2 line.
// ~12.8 MB, L2-resident.
__device__ __align__(16) __half2 g_tang[(size_t)NUM_CODES * (DIM / 2)];

// ---------------------------------------------------------------------------
// Pass 1: tang[c] = (atanh(min(||emb_c||,1-1e-7)) / max(||emb_c||,1e-15)) * emb_c
// One warp per TWO rows (half-warp per row): lane loads one float4 (16 floats
// x 16 lanes = 64 dims), 4-hop butterfly reduce within the half-warp, Taylor
// atanh(x)/x in the small-norm regime (data: ||x|| ~ 0.008), 8B fp16 store.
// DRAM-bound (38.4 MB): this version halves instruction overhead + blocks.
// ---------------------------------------------------------------------------
__global__ void __launch_bounds__(256) build_tangents(const float* __restrict__ emb) {
    const int warp = (blockIdx.x * blockDim.x + threadIdx.x) >> 5;
    const int lane = threadIdx.x & 31;
    const int half   = lane >> 4;            // which of the warp's 2 rows
    const int hl     = lane & 15;            // lane within half-warp
    const int row    = warp * 2 + half;
    if (row >= NUM_CODES) return;

    const float4 v = reinterpret_cast<const float4*>(emb + (size_t)row * DIM)[hl];
    float ss = v.x * v.x + v.y * v.y + v.z * v.z + v.w * v.w;
    #pragma unroll
    for (int o = 8; o; o >>= 1)
        ss += __shfl_xor_sync(0xffffffffu, ss, o);

    float s;
    if (ss < 0.09f) {
        // atanh(x)/x = 1 + y/3 + y^2/5 + y^3/7 + y^4/9, y = x^2 = ss.
        s = 1.0f + ss * (0.33333334f + ss * (0.2f + ss * (0.14285715f + ss * 0.11111111f)));
    } else {
        float n = fmaxf(sqrtf(ss), 1e-15f);
        float a = fminf(n, 1.0f - 1e-7f);
        s = atanhf(a) / n;
    }

    // Two half2 = 8 bytes per lane; 16 lanes cover the 128B row.
    __half2 h0 = __float22half2_rn(make_float2(s * v.x, s * v.y));
    __half2 h1 = __float22half2_rn(make_float2(s * v.z, s * v.w));
    __half2* dst = g_tang + (size_t)row * (DIM / 2) + hl * 2;
    dst[0] = h0;
    dst[1] = h1;
}

// half2 add on raw u32 payloads (HADD2).
__device__ __forceinline__ uint32_t hadd2u(uint32_t a, uint32_t b) {
    uint32_t r;
    asm("add.rn.f16x2 %0, %1, %2;" : "=r"(r) : "r"(a), "r"(b));
    return r;
}

// Convert one half2 to f32x2 and add into a packed f32x2 accumulator.
__device__ __forceinline__ void hacc2(uint32_t h2, unsigned long long& acc) {
    asm("{\n\t"
        ".reg .f16 l, h;\n\t"
        ".reg .f32 fl, fh;\n\t"
        ".reg .b64 fv;\n\t"
        "mov.b32 {l, h}, %1;\n\t"
        "cvt.f32.f16 fl, l;\n\t"
        "cvt.f32.f16 fh, h;\n\t"
        "mov.b64 fv, {fl, fh};\n\t"
        "add.rn.f32x2 %0, %0, fv;\n\t"
        "}" : "+l"(acc) : "r"(h2));
}

// Predicated 16B gather: returns zeros when pred is false, no memory traffic.
__device__ __forceinline__ uint4 gather_pred(bool pred, const char* p) {
    uint4 r = make_uint4(0u, 0u, 0u, 0u);
    if (pred) r = *reinterpret_cast<const uint4*>(p);
    return r;
}

// ---------------------------------------------------------------------------
// Pass 2: out[visit] = mean over valid codes of tang[code].
// AT THE LTS CEILING (measured 48.9% of theoretical peak = ~96% of the 6300
// B/cyc practical cap): ~315MB of irreducible L2 traffic in ~25us. Structure:
// quarter-warp per visit; ids staged via smem (coalesced, 8x fewer id
// wavefronts); predicated gathers (squashed pad loads cost no wavefront);
// 8-wide fp16 tree, packed f32x2 accumulation.
// ---------------------------------------------------------------------------
__global__ void __launch_bounds__(256, 5) visit_mean(const int* __restrict__ ids,
                                                     float* __restrict__ out) {
    __shared__ __align__(16) uint4 sids[IDV4_PER_BLOCK];   // 6 KB

    const int tid  = threadIdx.x;
    const int warp = tid >> 5;
    const int lane = tid & 31;
    const int quarter = lane >> 3;
    const int ql      = lane & 7;          // 16B chunk within row: dims [8ql, 8ql+8)

    // Stage the block's ids: 384 uint4, coalesced.
    {
        const uint4* __restrict__ gids = reinterpret_cast<const uint4*>(
            ids + (size_t)blockIdx.x * VISITS_PER_BLOCK * LCODES);
        sids[tid] = __ldg(gids + tid);                       // 0..255
        if (tid < IDV4_PER_BLOCK - 256)
            sids[256 + tid] = __ldg(gids + 256 + tid);       // 256..383
    }
    __syncthreads();

    const int lvisit = warp * 4 + quarter;                   // visit within block
    const int visit  = blockIdx.x * VISITS_PER_BLOCK + lvisit;
    const uint4* __restrict__ vid4 = sids + lvisit * IDV4_PER_VISIT;

    const char* __restrict__ base = reinterpret_cast<const char*>(g_tang) + ql * 16;

    unsigned long long acc[4] = {0ull, 0ull, 0ull, 0ull};
    int cnt = 0;

    #pragma unroll
    for (int gg = 0; gg < 6; gg++) {       // 6 supergroups of 8 codes
        const uint4 idv0 = vid4[2 * gg];
        const uint4 idv1 = vid4[2 * gg + 1];

        const int i0 = (int)idv0.x, i1 = (int)idv0.y, i2 = (int)idv0.z, i3 = (int)idv0.w;
        const int i4 = (int)idv1.x, i5 = (int)idv1.y, i6 = (int)idv1.z, i7 = (int)idv1.w;
        cnt += (i0 >= 0) + (i1 >= 0) + (i2 >= 0) + (i3 >= 0)
             + (i4 >= 0) + (i5 >= 0) + (i6 >= 0) + (i7 >= 0);

        const uint4 a = gather_pred(i0 >= 0, base + (size_t)(unsigned)i0 * 128u);
        const uint4 b = gather_pred(i1 >= 0, base + (size_t)(unsigned)i1 * 128u);
        const uint4 c = gather_pred(i2 >= 0, base + (size_t)(unsigned)i2 * 128u);
        const uint4 d = gather_pred(i3 >= 0, base + (size_t)(unsigned)i3 * 128u);
        const uint4 e = gather_pred(i4 >= 0, base + (size_t)(unsigned)i4 * 128u);
        const uint4 h = gather_pred(i5 >= 0, base + (size_t)(unsigned)i5 * 128u);
        const uint4 p = gather_pred(i6 >= 0, base + (size_t)(unsigned)i6 * 128u);
        const uint4 q = gather_pred(i7 >= 0, base + (size_t)(unsigned)i7 * 128u);

        // 8-wide balanced fp16 tree per component, single fp32 accumulate.
        hacc2(hadd2u(hadd2u(hadd2u(a.x, b.x), hadd2u(c.x, d.x)),
                     hadd2u(hadd2u(e.x, h.x), hadd2u(p.x, q.x))), acc[0]);
        hacc2(hadd2u(hadd2u(hadd2u(a.y, b.y), hadd2u(c.y, d.y)),
                     hadd2u(hadd2u(e.y, h.y), hadd2u(p.y, q.y))), acc[1]);
        hacc2(hadd2u(hadd2u(hadd2u(a.z, b.z), hadd2u(c.z, d.z)),
                     hadd2u(hadd2u(e.z, h.z), hadd2u(p.z, q.z))), acc[2]);
        hacc2(hadd2u(hadd2u(hadd2u(a.w, b.w), hadd2u(c.w, d.w)),
                     hadd2u(hadd2u(e.w, h.w), hadd2u(p.w, q.w))), acc[3]);
    }

    float f[8];
    #pragma unroll
    for (int j = 0; j < 4; j++) {
        f[2 * j]     = __uint_as_float((unsigned)(acc[j] & 0xffffffffull));
        f[2 * j + 1] = __uint_as_float((unsigned)(acc[j] >> 32));
    }

    const float inv = __fdividef(1.0f, fmaxf((float)cnt, 1.0f));
    float4 o0 = make_float4(f[0] * inv, f[1] * inv, f[2] * inv, f[3] * inv);
    float4 o1 = make_float4(f[4] * inv, f[5] * inv, f[6] * inv, f[7] * inv);
    float4* op = reinterpret_cast<float4*>(out + (size_t)visit * DIM + ql * 8);
    op[0] = o0;
    op[1] = o1;
}

extern "C" void kernel_launch(void* const* d_in, const int* in_sizes, int n_in,
                              void* d_out, int out_size) {
    const int*   code_ids = (const int*)d_in[0];   // [N, L] int32, -1 = pad
    const float* emb      = (const float*)d_in[1]; // [NUM_CODES, DIM] fp32
    float*       out      = (float*)d_out;         // [N, DIM] fp32

    (void)in_sizes; (void)n_in; (void)out_size;

    // Pass 1: 2 rows per warp -> 50000 warps -> 6250 blocks of 8 warps.
    build_tangents<<<(NUM_CODES / 2 + 7) / 8, 256>>>(emb);
    // Pass 2: 32 visits per 256-thread block: 65536 / 32 = 2048 blocks.
    visit_mean<<<NVISITS / VISITS_PER_BLOCK, 256>>>(code_ids, out);
}

// round 16
// speedup vs baseline: 1.1807x; 1.0432x over previous
#include <cuda_runtime.h>
#include <cuda_fp16.h>
#include <cstdint>

#define NUM_CODES 100000
#define DIM 64
#define NVISITS 65536
#define LCODES 48
#define VISITS_PER_BLOCK 16
#define BLOCK_THREADS 128
#define IDV4_PER_VISIT 12                       // 48 ids = 12 uint4
#define IDV4_PER_BLOCK (VISITS_PER_BLOCK * IDV4_PER_VISIT)   // 192

// fp16 pre-scaled tangent table. Row = 64 halfs = 128 B = one L2 line.
// ~12.8 MB, L2-resident.
__device__ __align__(16) __half2 g_tang[(size_t)NUM_CODES * (DIM / 2)];

// ---------------------------------------------------------------------------
// Pass 1: tang[c] = (atanh(min(||emb_c||,1-1e-7)) / max(||emb_c||,1e-15)) * emb_c
// One warp per TWO rows (half-warp per row): lane loads one float4, 4-hop
// butterfly reduce within the half-warp, Taylor atanh(x)/x in the small-norm
// regime (data: ||x|| ~ 0.008), 8B fp16 store. At its DRAM/L2 floor.
// ---------------------------------------------------------------------------
__global__ void __launch_bounds__(256) build_tangents(const float* __restrict__ emb) {
    const int warp = (blockIdx.x * blockDim.x + threadIdx.x) >> 5;
    const int lane = threadIdx.x & 31;
    const int half   = lane >> 4;            // which of the warp's 2 rows
    const int hl     = lane & 15;            // lane within half-warp
    const int row    = warp * 2 + half;
    if (row >= NUM_CODES) return;

    const float4 v = reinterpret_cast<const float4*>(emb + (size_t)row * DIM)[hl];
    float ss = v.x * v.x + v.y * v.y + v.z * v.z + v.w * v.w;
    #pragma unroll
    for (int o = 8; o; o >>= 1)
        ss += __shfl_xor_sync(0xffffffffu, ss, o);

    float s;
    if (ss < 0.09f) {
        // atanh(x)/x = 1 + y/3 + y^2/5 + y^3/7 + y^4/9, y = x^2 = ss.
        s = 1.0f + ss * (0.33333334f + ss * (0.2f + ss * (0.14285715f + ss * 0.11111111f)));
    } else {
        float n = fmaxf(sqrtf(ss), 1e-15f);
        float a = fminf(n, 1.0f - 1e-7f);
        s = atanhf(a) / n;
    }

    __half2 h0 = __float22half2_rn(make_float2(s * v.x, s * v.y));
    __half2 h1 = __float22half2_rn(make_float2(s * v.z, s * v.w));
    __half2* dst = g_tang + (size_t)row * (DIM / 2) + hl * 2;
    dst[0] = h0;
    dst[1] = h1;
}

// half2 add on raw u32 payloads (HADD2).
__device__ __forceinline__ uint32_t hadd2u(uint32_t a, uint32_t b) {
    uint32_t r;
    asm("add.rn.f16x2 %0, %1, %2;" : "=r"(r) : "r"(a), "r"(b));
    return r;
}

// Convert one half2 to f32x2 and add into a packed f32x2 accumulator.
__device__ __forceinline__ void hacc2(uint32_t h2, unsigned long long& acc) {
    asm("{\n\t"
        ".reg .f16 l, h;\n\t"
        ".reg .f32 fl, fh;\n\t"
        ".reg .b64 fv;\n\t"
        "mov.b32 {l, h}, %1;\n\t"
        "cvt.f32.f16 fl, l;\n\t"
        "cvt.f32.f16 fh, h;\n\t"
        "mov.b64 fv, {fl, fh};\n\t"
        "add.rn.f32x2 %0, %0, fv;\n\t"
        "}" : "+l"(acc) : "r"(h2));
}

// Predicated 16B gather: returns zeros when pred is false, no memory traffic.
__device__ __forceinline__ uint4 gather_pred(bool pred, const char* p) {
    uint4 r = make_uint4(0u, 0u, 0u, 0u);
    if (pred) r = *reinterpret_cast<const uint4*>(p);
    return r;
}

// ---------------------------------------------------------------------------
// Pass 2: out[visit] = mean over valid codes of tang[code].
// AT THE LTS CEILING (~311MB of irreducible L2 traffic at ~93% of the 6300
// B/cyc practical cap). Structure: quarter-warp per visit; ids staged via
// smem (coalesced); predicated gathers (squashed pad loads cost no
// wavefront); 8-wide fp16 tree, packed f32x2 accumulation.
// This round: 128-thread blocks (16 visits, 4096 blocks, 10 blocks/SM =
// same 40 warps/SM) for 2x finer wave-quantization granularity -- grid was
// 2.77 waves of 740 with a ~57%-empty tail wave.
// ---------------------------------------------------------------------------
__global__ void __launch_bounds__(BLOCK_THREADS, 10) visit_mean(
        const int* __restrict__ ids, float* __restrict__ out) {
    __shared__ __align__(16) uint4 sids[IDV4_PER_BLOCK];   // 3 KB

    const int tid  = threadIdx.x;
    const int warp = tid >> 5;
    const int lane = tid & 31;
    const int quarter = lane >> 3;
    const int ql      = lane & 7;          // 16B chunk within row: dims [8ql, 8ql+8)

    // Stage the block's ids: 192 uint4, coalesced (128 threads -> 1.5 rounds).
    {
        const uint4* __restrict__ gids = reinterpret_cast<const uint4*>(
            ids + (size_t)blockIdx.x * VISITS_PER_BLOCK * LCODES);
        sids[tid] = __ldg(gids + tid);                       // 0..127
        if (tid < IDV4_PER_BLOCK - BLOCK_THREADS)
            sids[BLOCK_THREADS + tid] = __ldg(gids + BLOCK_THREADS + tid); // 128..191
    }
    __syncthreads();

    const int lvisit = warp * 4 + quarter;                   // visit within block
    const int visit  = blockIdx.x * VISITS_PER_BLOCK + lvisit;
    const uint4* __restrict__ vid4 = sids + lvisit * IDV4_PER_VISIT;

    const char* __restrict__ base = reinterpret_cast<const char*>(g_tang) + ql * 16;

    unsigned long long acc[4] = {0ull, 0ull, 0ull, 0ull};
    int cnt = 0;

    #pragma unroll
    for (int gg = 0; gg < 6; gg++) {       // 6 supergroups of 8 codes
        const uint4 idv0 = vid4[2 * gg];
        const uint4 idv1 = vid4[2 * gg + 1];

        const int i0 = (int)idv0.x, i1 = (int)idv0.y, i2 = (int)idv0.z, i3 = (int)idv0.w;
        const int i4 = (int)idv1.x, i5 = (int)idv1.y, i6 = (int)idv1.z, i7 = (int)idv1.w;
        cnt += (i0 >= 0) + (i1 >= 0) + (i2 >= 0) + (i3 >= 0)
             + (i4 >= 0) + (i5 >= 0) + (i6 >= 0) + (i7 >= 0);

        const uint4 a = gather_pred(i0 >= 0, base + (size_t)(unsigned)i0 * 128u);
        const uint4 b = gather_pred(i1 >= 0, base + (size_t)(unsigned)i1 * 128u);
        const uint4 c = gather_pred(i2 >= 0, base + (size_t)(unsigned)i2 * 128u);
        const uint4 d = gather_pred(i3 >= 0, base + (size_t)(unsigned)i3 * 128u);
        const uint4 e = gather_pred(i4 >= 0, base + (size_t)(unsigned)i4 * 128u);
        const uint4 h = gather_pred(i5 >= 0, base + (size_t)(unsigned)i5 * 128u);
        const uint4 p = gather_pred(i6 >= 0, base + (size_t)(unsigned)i6 * 128u);
        const uint4 q = gather_pred(i7 >= 0, base + (size_t)(unsigned)i7 * 128u);

        // 8-wide balanced fp16 tree per component, single fp32 accumulate.
        hacc2(hadd2u(hadd2u(hadd2u(a.x, b.x), hadd2u(c.x, d.x)),
                     hadd2u(hadd2u(e.x, h.x), hadd2u(p.x, q.x))), acc[0]);
        hacc2(hadd2u(hadd2u(hadd2u(a.y, b.y), hadd2u(c.y, d.y)),
                     hadd2u(hadd2u(e.y, h.y), hadd2u(p.y, q.y))), acc[1]);
        hacc2(hadd2u(hadd2u(hadd2u(a.z, b.z), hadd2u(c.z, d.z)),
                     hadd2u(hadd2u(e.z, h.z), hadd2u(p.z, q.z))), acc[2]);
        hacc2(hadd2u(hadd2u(hadd2u(a.w, b.w), hadd2u(c.w, d.w)),
                     hadd2u(hadd2u(e.w, h.w), hadd2u(p.w, q.w))), acc[3]);
    }

    float f[8];
    #pragma unroll
    for (int j = 0; j < 4; j++) {
        f[2 * j]     = __uint_as_float((unsigned)(acc[j] & 0xffffffffull));
        f[2 * j + 1] = __uint_as_float((unsigned)(acc[j] >> 32));
    }

    const float inv = __fdividef(1.0f, fmaxf((float)cnt, 1.0f));
    float4 o0 = make_float4(f[0] * inv, f[1] * inv, f[2] * inv, f[3] * inv);
    float4 o1 = make_float4(f[4] * inv, f[5] * inv, f[6] * inv, f[7] * inv);
    float4* op = reinterpret_cast<float4*>(out + (size_t)visit * DIM + ql * 8);
    op[0] = o0;
    op[1] = o1;
}

extern "C" void kernel_launch(void* const* d_in, const int* in_sizes, int n_in,
                              void* d_out, int out_size) {
    const int*   code_ids = (const int*)d_in[0];   // [N, L] int32, -1 = pad
    const float* emb      = (const float*)d_in[1]; // [NUM_CODES, DIM] fp32
    float*       out      = (float*)d_out;         // [N, DIM] fp32

    (void)in_sizes; (void)n_in; (void)out_size;

    // Pass 1: 2 rows per warp -> 50000 warps -> 6250 blocks of 8 warps.
    build_tangents<<<(NUM_CODES / 2 + 7) / 8, 256>>>(emb);
    // Pass 2: 16 visits per 128-thread block: 65536 / 16 = 4096 blocks.
    visit_mean<<<NVISITS / VISITS_PER_BLOCK, BLOCK_THREADS>>>(code_ids, out);
}

// round 17
// speedup vs baseline: 1.2267x; 1.0390x over previous
#include <cuda_runtime.h>
#include <cuda_fp16.h>
#include <cstdint>

#define NUM_CODES 100000
#define DIM 64
#define NVISITS 65536
#define LCODES 48
#define VISITS_PER_BLOCK 8
#define BLOCK_THREADS 64
#define IDV4_PER_VISIT 12                       // 48 ids = 12 uint4
#define IDV4_PER_BLOCK (VISITS_PER_BLOCK * IDV4_PER_VISIT)   // 96

// fp16 pre-scaled tangent table. Row = 64 halfs = 128 B = one L2 line.
// ~12.8 MB, L2-resident.
__device__ __align__(16) __half2 g_tang[(size_t)NUM_CODES * (DIM / 2)];

// ---------------------------------------------------------------------------
// Pass 1: tang[c] = (atanh(min(||emb_c||,1-1e-7)) / max(||emb_c||,1e-15)) * emb_c
// One warp per TWO rows (half-warp per row): lane loads one float4, 4-hop
// butterfly reduce within the half-warp, Taylor atanh(x)/x in the small-norm
// regime (data: ||x|| ~ 0.008), 8B fp16 store. At its DRAM/L2 floor.
// ---------------------------------------------------------------------------
__global__ void __launch_bounds__(256) build_tangents(const float* __restrict__ emb) {
    const int warp = (blockIdx.x * blockDim.x + threadIdx.x) >> 5;
    const int lane = threadIdx.x & 31;
    const int half   = lane >> 4;            // which of the warp's 2 rows
    const int hl     = lane & 15;            // lane within half-warp
    const int row    = warp * 2 + half;
    if (row >= NUM_CODES) return;

    const float4 v = reinterpret_cast<const float4*>(emb + (size_t)row * DIM)[hl];
    float ss = v.x * v.x + v.y * v.y + v.z * v.z + v.w * v.w;
    #pragma unroll
    for (int o = 8; o; o >>= 1)
        ss += __shfl_xor_sync(0xffffffffu, ss, o);

    float s;
    if (ss < 0.09f) {
        // atanh(x)/x = 1 + y/3 + y^2/5 + y^3/7 + y^4/9, y = x^2 = ss.
        s = 1.0f + ss * (0.33333334f + ss * (0.2f + ss * (0.14285715f + ss * 0.11111111f)));
    } else {
        float n = fmaxf(sqrtf(ss), 1e-15f);
        float a = fminf(n, 1.0f - 1e-7f);
        s = atanhf(a) / n;
    }

    __half2 h0 = __float22half2_rn(make_float2(s * v.x, s * v.y));
    __half2 h1 = __float22half2_rn(make_float2(s * v.z, s * v.w));
    __half2* dst = g_tang + (size_t)row * (DIM / 2) + hl * 2;
    dst[0] = h0;
    dst[1] = h1;
}

// half2 add on raw u32 payloads (HADD2).
__device__ __forceinline__ uint32_t hadd2u(uint32_t a, uint32_t b) {
    uint32_t r;
    asm("add.rn.f16x2 %0, %1, %2;" : "=r"(r) : "r"(a), "r"(b));
    return r;
}

// Convert one half2 to f32x2 and add into a packed f32x2 accumulator.
__device__ __forceinline__ void hacc2(uint32_t h2, unsigned long long& acc) {
    asm("{\n\t"
        ".reg .f16 l, h;\n\t"
        ".reg .f32 fl, fh;\n\t"
        ".reg .b64 fv;\n\t"
        "mov.b32 {l, h}, %1;\n\t"
        "cvt.f32.f16 fl, l;\n\t"
        "cvt.f32.f16 fh, h;\n\t"
        "mov.b64 fv, {fl, fh};\n\t"
        "add.rn.f32x2 %0, %0, fv;\n\t"
        "}" : "+l"(acc) : "r"(h2));
}

// Predicated 16B gather: returns zeros when pred is false, no memory traffic.
__device__ __forceinline__ uint4 gather_pred(bool pred, const char* p) {
    uint4 r = make_uint4(0u, 0u, 0u, 0u);
    if (pred) r = *reinterpret_cast<const uint4*>(p);
    return r;
}

// ---------------------------------------------------------------------------
// Pass 2: out[visit] = mean over valid codes of tang[code].
// AT THE LTS CEILING (~311MB of irreducible L2 traffic at ~96% of the 6300
// B/cyc practical cap). Structure: quarter-warp per visit; ids staged via
// smem (coalesced); predicated gathers (squashed pad loads cost no
// wavefront); 8-wide fp16 tree, packed f32x2 accumulation.
// This round: 64-thread blocks (8 visits, 8192 blocks) -- same ~40 resident
// warps/SM but half the scheduling quantum, shrinking the ~8% wave-tail
// quantization loss of the 2.77-wave grid.
// ---------------------------------------------------------------------------
__global__ void __launch_bounds__(BLOCK_THREADS, 20) visit_mean(
        const int* __restrict__ ids, float* __restrict__ out) {
    __shared__ __align__(16) uint4 sids[IDV4_PER_BLOCK];   // 1.5 KB

    const int tid  = threadIdx.x;
    const int warp = tid >> 5;
    const int lane = tid & 31;
    const int quarter = lane >> 3;
    const int ql      = lane & 7;          // 16B chunk within row: dims [8ql, 8ql+8)

    // Stage the block's ids: 96 uint4, coalesced (64 threads -> 1.5 rounds).
    {
        const uint4* __restrict__ gids = reinterpret_cast<const uint4*>(
            ids + (size_t)blockIdx.x * VISITS_PER_BLOCK * LCODES);
        sids[tid] = __ldg(gids + tid);                       // 0..63
        if (tid < IDV4_PER_BLOCK - BLOCK_THREADS)
            sids[BLOCK_THREADS + tid] = __ldg(gids + BLOCK_THREADS + tid); // 64..95
    }
    __syncthreads();

    const int lvisit = warp * 4 + quarter;                   // visit within block
    const int visit  = blockIdx.x * VISITS_PER_BLOCK + lvisit;
    const uint4* __restrict__ vid4 = sids + lvisit * IDV4_PER_VISIT;

    const char* __restrict__ base = reinterpret_cast<const char*>(g_tang) + ql * 16;

    unsigned long long acc[4] = {0ull, 0ull, 0ull, 0ull};
    int cnt = 0;

    #pragma unroll
    for (int gg = 0; gg < 6; gg++) {       // 6 supergroups of 8 codes
        const uint4 idv0 = vid4[2 * gg];
        const uint4 idv1 = vid4[2 * gg + 1];

        const int i0 = (int)idv0.x, i1 = (int)idv0.y, i2 = (int)idv0.z, i3 = (int)idv0.w;
        const int i4 = (int)idv1.x, i5 = (int)idv1.y, i6 = (int)idv1.z, i7 = (int)idv1.w;
        cnt += (i0 >= 0) + (i1 >= 0) + (i2 >= 0) + (i3 >= 0)
             + (i4 >= 0) + (i5 >= 0) + (i6 >= 0) + (i7 >= 0);

        const uint4 a = gather_pred(i0 >= 0, base + (size_t)(unsigned)i0 * 128u);
        const uint4 b = gather_pred(i1 >= 0, base + (size_t)(unsigned)i1 * 128u);
        const uint4 c = gather_pred(i2 >= 0, base + (size_t)(unsigned)i2 * 128u);
        const uint4 d = gather_pred(i3 >= 0, base + (size_t)(unsigned)i3 * 128u);
        const uint4 e = gather_pred(i4 >= 0, base + (size_t)(unsigned)i4 * 128u);
        const uint4 h = gather_pred(i5 >= 0, base + (size_t)(unsigned)i5 * 128u);
        const uint4 p = gather_pred(i6 >= 0, base + (size_t)(unsigned)i6 * 128u);
        const uint4 q = gather_pred(i7 >= 0, base + (size_t)(unsigned)i7 * 128u);

        // 8-wide balanced fp16 tree per component, single fp32 accumulate.
        hacc2(hadd2u(hadd2u(hadd2u(a.x, b.x), hadd2u(c.x, d.x)),
                     hadd2u(hadd2u(e.x, h.x), hadd2u(p.x, q.x))), acc[0]);
        hacc2(hadd2u(hadd2u(hadd2u(a.y, b.y), hadd2u(c.y, d.y)),
                     hadd2u(hadd2u(e.y, h.y), hadd2u(p.y, q.y))), acc[1]);
        hacc2(hadd2u(hadd2u(hadd2u(a.z, b.z), hadd2u(c.z, d.z)),
                     hadd2u(hadd2u(e.z, h.z), hadd2u(p.z, q.z))), acc[2]);
        hacc2(hadd2u(hadd2u(hadd2u(a.w, b.w), hadd2u(c.w, d.w)),
                     hadd2u(hadd2u(e.w, h.w), hadd2u(p.w, q.w))), acc[3]);
    }

    float f[8];
    #pragma unroll
    for (int j = 0; j < 4; j++) {
        f[2 * j]     = __uint_as_float((unsigned)(acc[j] & 0xffffffffull));
        f[2 * j + 1] = __uint_as_float((unsigned)(acc[j] >> 32));
    }

    const float inv = __fdividef(1.0f, fmaxf((float)cnt, 1.0f));
    float4 o0 = make_float4(f[0] * inv, f[1] * inv, f[2] * inv, f[3] * inv);
    float4 o1 = make_float4(f[4] * inv, f[5] * inv, f[6] * inv, f[7] * inv);
    float4* op = reinterpret_cast<float4*>(out + (size_t)visit * DIM + ql * 8);
    op[0] = o0;
    op[1] = o1;
}

extern "C" void kernel_launch(void* const* d_in, const int* in_sizes, int n_in,
                              void* d_out, int out_size) {
    const int*   code_ids = (const int*)d_in[0];   // [N, L] int32, -1 = pad
    const float* emb      = (const float*)d_in[1]; // [NUM_CODES, DIM] fp32
    float*       out      = (float*)d_out;         // [N, DIM] fp32

    (void)in_sizes; (void)n_in; (void)out_size;

    // Pass 1: 2 rows per warp -> 50000 warps -> 6250 blocks of 8 warps.
    build_tangents<<<(NUM_CODES / 2 + 7) / 8, 256>>>(emb);
    // Pass 2: 8 visits per 64-thread block: 65536 / 8 = 8192 blocks.
    visit_mean<<<NVISITS / VISITS_PER_BLOCK, BLOCK_THREADS>>>(code_ids, out);
}